// round 15
// baseline (speedup 1.0000x reference)
#include <cuda_runtime.h>
#include <cuda_fp16.h>
#include <cstdint>
#include <math.h>

// Problem constants
#define BATCH   512
#define NTOK    64
#define C_DIM   768
#define K2DIM   2304          // 3*C
#define TOKENS  (BATCH * NTOK)   // 32768

// ---------------- device scratch (no allocation allowed) ----------------
__device__ __half g_xfuse[(size_t)TOKENS * K2DIM];   // [token][3C], fp16
__device__ __half g_y[(size_t)TOKENS * C_DIM];       // stage-2 output, fp16
__device__ __half g_fc2p[C_DIM * K2DIM];             // fc2 * ln2_w, fp16
__device__ __half g_projp[C_DIM * C_DIM];            // proj_w, fp16
__device__ float  g_colsum[C_DIM];                   // sum_k ln2_w[k]*fc2[o,k]
__device__ float  g_bsum[C_DIM];                     // sum_k ln2_b[k]*fc2[o,k]
__device__ unsigned g_queue;                         // persistent work ticket
__device__ unsigned g_pdone[6];                      // prep rows done per n-block (tgt 128)
__device__ unsigned g_s1done[TOKENS / 128];          // stage1 parts per M-block (tgt 6)
__device__ unsigned g_mdone[TOKENS / 128];           // K2 tiles done per M-block (tgt 6)

#define T_PREP   768
#define T_S1     1536
#define T_K2     1536
#define T_K3     1536
#define OFF_S1   (T_PREP)
#define OFF_K2   (OFF_S1 + T_S1)
#define OFF_K3   (OFF_K2 + T_K2)
#define N_TILES  (OFF_K3 + T_K3)

// ---------------- helpers ----------------
__device__ __forceinline__ float tanh_fast(float x) {
    float y;
    asm("tanh.approx.f32 %0, %1;" : "=f"(y) : "f"(x));
    return y;
}
__device__ __forceinline__ float gelu_t(float x) {
    float u = 0.7978845608028654f * (x + 0.044715f * x * x * x);
    return 0.5f * x * (1.0f + tanh_fast(u));
}
__device__ __forceinline__ void st_half_cs(__half* p, __half v) {
    short b = *reinterpret_cast<short*>(&v);
    __stcs(reinterpret_cast<short*>(p), b);
}

// ---------------- GEMM tile (R10 config) as a device function ----------------
#define BM 128
#define BN 128
#define BK 32
#define LDH 40
#define NSLOT 5
#define TILE_H (BM * LDH)
#define STAGE_BYTES (2 * TILE_H * 2)
#define SMEM_BYTES (NSLOT * STAGE_BYTES)      // 102400 B
#define GTHREADS 256

__device__ __forceinline__ void cp16(uint32_t smem, const void* g) {
    asm volatile("cp.async.cg.shared.global [%0], [%1], 16;\n" :: "r"(smem), "l"(g));
}

template<int KDIM, bool FUSE>
__device__ __forceinline__ void gemm_tile(
        uint32_t smem_u, float* s_m, float* s_r, float* s_c0, float* s_c1,
        const __half* __restrict__ Ag, const __half* __restrict__ Bg,
        const float* __restrict__ bias,
        float* __restrict__ CoutF, __half* __restrict__ CoutH,
        int bx, int by) {
    int tid = threadIdx.x;
    int rowA0 = by * BM;
    int colB0 = bx * BN;
    const __half* Abase = Ag + (size_t)rowA0 * KDIM;
    const __half* Bbase = Bg + (size_t)colB0 * KDIM;

    int lr = tid >> 1;
    int lc = (tid & 1) * 16;
    uint32_t sOffA = (uint32_t)((lr * LDH + lc) * 2);
    uint32_t sOffB = sOffA + TILE_H * 2;

    auto load_body = [&](int slot, int kt) {
        uint32_t base = smem_u + (uint32_t)slot * STAGE_BYTES;
        const __half* a0 = Abase + (size_t)lr * KDIM + kt * BK + lc;
        cp16(base + sOffA,      a0);
        cp16(base + sOffA + 16, a0 + 8);
        const __half* b0 = Bbase + (size_t)lr * KDIM + kt * BK + lc;
        cp16(base + sOffB,      b0);
        cp16(base + sOffB + 16, b0 + 8);
    };

    const int KT = KDIM / BK;
    #pragma unroll
    for (int p = 0; p < 3; p++) {
        load_body(p, p);
        asm volatile("cp.async.commit_group;\n");
    }

    int wid = tid >> 5, lane = tid & 31;
    int wm = (wid & 1) * 64;
    int wn = (wid >> 1) * 32;

    uint32_t offA[4];
    #pragma unroll
    for (int mm = 0; mm < 4; mm++) {
        int row = wm + mm * 16 + (lane & 15);
        int kb  = lane >> 4;
        offA[mm] = (uint32_t)((row * LDH + kb * 8) * 2);
    }
    uint32_t offB[2];
    #pragma unroll
    for (int nn2 = 0; nn2 < 2; nn2++) {
        int n  = wn + nn2 * 16 + (lane & 7) + ((lane >> 4) ? 8 : 0);
        int kb = (lane >> 3) & 1;
        offB[nn2] = (uint32_t)((n * LDH + kb * 8) * 2 + TILE_H * 2);
    }

    float acc[4][4][4];
    #pragma unroll
    for (int a = 0; a < 4; a++)
        #pragma unroll
        for (int b2 = 0; b2 < 4; b2++)
            #pragma unroll
            for (int c2 = 0; c2 < 4; c2++) acc[a][b2][c2] = 0.f;

    float rsum = 0.f, rsq = 0.f;
    int srow = tid & 127, skh = (tid >> 7) * 16;
    uint32_t statOff = (uint32_t)((srow * LDH + skh) * 2);

    auto compute_stage = [&](int slot) {
        uint32_t stage = smem_u + (uint32_t)slot * STAGE_BYTES;

        if (FUSE) {
            uint4 q0, q1;
            asm volatile("ld.shared.v4.u32 {%0,%1,%2,%3}, [%4];"
                         : "=r"(q0.x), "=r"(q0.y), "=r"(q0.z), "=r"(q0.w)
                         : "r"(stage + statOff));
            asm volatile("ld.shared.v4.u32 {%0,%1,%2,%3}, [%4];"
                         : "=r"(q1.x), "=r"(q1.y), "=r"(q1.z), "=r"(q1.w)
                         : "r"(stage + statOff + 16));
            const uint32_t wv[8] = {q0.x, q0.y, q0.z, q0.w, q1.x, q1.y, q1.z, q1.w};
            #pragma unroll
            for (int wq = 0; wq < 8; wq++) {
                __half2 hv = *reinterpret_cast<const __half2*>(&wv[wq]);
                float2 f = __half22float2(hv);
                rsum += f.x + f.y;
                rsq  += f.x * f.x + f.y * f.y;
            }
        }

        #pragma unroll
        for (int kk = 0; kk < BK; kk += 16) {
            uint32_t af[4][4], bf[2][4];
            #pragma unroll
            for (int mm = 0; mm < 4; mm++)
                asm volatile(
                    "ldmatrix.sync.aligned.m8n8.x4.shared.b16 {%0,%1,%2,%3}, [%4];\n"
                    : "=r"(af[mm][0]), "=r"(af[mm][1]), "=r"(af[mm][2]), "=r"(af[mm][3])
                    : "r"(stage + offA[mm] + kk * 2));
            #pragma unroll
            for (int nn2 = 0; nn2 < 2; nn2++)
                asm volatile(
                    "ldmatrix.sync.aligned.m8n8.x4.shared.b16 {%0,%1,%2,%3}, [%4];\n"
                    : "=r"(bf[nn2][0]), "=r"(bf[nn2][1]), "=r"(bf[nn2][2]), "=r"(bf[nn2][3])
                    : "r"(stage + offB[nn2] + kk * 2));

            #pragma unroll
            for (int mm = 0; mm < 4; mm++)
                #pragma unroll
                for (int nn = 0; nn < 4; nn++) {
                    const uint32_t b0 = bf[nn >> 1][(nn & 1) * 2 + 0];
                    const uint32_t b1 = bf[nn >> 1][(nn & 1) * 2 + 1];
                    asm volatile(
                        "mma.sync.aligned.m16n8k16.row.col.f32.f16.f16.f32 "
                        "{%0,%1,%2,%3}, {%4,%5,%6,%7}, {%8,%9}, {%0,%1,%2,%3};\n"
                        : "+f"(acc[mm][nn][0]), "+f"(acc[mm][nn][1]),
                          "+f"(acc[mm][nn][2]), "+f"(acc[mm][nn][3])
                        : "r"(af[mm][0]), "r"(af[mm][1]), "r"(af[mm][2]), "r"(af[mm][3]),
                          "r"(b0), "r"(b1));
                }
        }
    };

    int slotC = 0, slotP = 3;
    for (int s = 0; s < KT; s += 2) {
        asm volatile("cp.async.wait_group %0;\n" :: "n"(1));
        __syncthreads();

        if (s + 3 < KT) load_body(slotP, s + 3);
        asm volatile("cp.async.commit_group;\n");
        int slotP2 = slotP + 1; if (slotP2 >= NSLOT) slotP2 -= NSLOT;
        if (s + 4 < KT) load_body(slotP2, s + 4);
        asm volatile("cp.async.commit_group;\n");

        compute_stage(slotC);
        int slotC2 = slotC + 1; if (slotC2 >= NSLOT) slotC2 -= NSLOT;
        compute_stage(slotC2);

        slotC += 2; if (slotC >= NSLOT) slotC -= NSLOT;
        slotP += 2; if (slotP >= NSLOT) slotP -= NSLOT;
    }
    asm volatile("cp.async.wait_group 0;\n");   // drain before smem reuse

    // ---- epilogue ----
    __syncthreads();
    if (FUSE) {
        if (tid < 128) { s_m[tid] = rsum; s_r[tid] = rsq; }
        __syncthreads();
        if (tid >= 128) { s_m[tid - 128] += rsum; s_r[tid - 128] += rsq; }
        __syncthreads();
        if (tid < 128) {
            float mu  = s_m[tid] * (1.0f / (float)KDIM);
            float var = s_r[tid] * (1.0f / (float)KDIM) - mu * mu;
            s_m[tid] = mu;
            s_r[tid] = rsqrtf(var + 1e-5f);
            s_c0[tid] = g_colsum[colB0 + tid];
            s_c1[tid] = g_bsum[colB0 + tid];
        }
        __syncthreads();
    } else {
        if (tid < 128) s_c1[tid] = bias[colB0 + tid];
        __syncthreads();
    }

    int g = lane >> 2, t4 = lane & 3;
    #pragma unroll
    for (int mm = 0; mm < 4; mm++) {
        #pragma unroll
        for (int nn = 0; nn < 4; nn++) {
            #pragma unroll
            for (int rh = 0; rh < 2; rh++) {
                int rl = wm + mm * 16 + g + rh * 8;
                int cl = wn + nn * 8 + 2 * t4;
                float v0 = acc[mm][nn][rh * 2 + 0];
                float v1 = acc[mm][nn][rh * 2 + 1];
                if (FUSE) {
                    float p0 = s_r[rl] * (v0 - s_m[rl] * s_c0[cl])     + s_c1[cl];
                    float p1 = s_r[rl] * (v1 - s_m[rl] * s_c0[cl + 1]) + s_c1[cl + 1];
                    __half2 o = __floats2half2_rn(gelu_t(p0), gelu_t(p1));
                    *reinterpret_cast<__half2*>(
                        CoutH + (size_t)(rowA0 + rl) * C_DIM + colB0 + cl) = o;
                } else {
                    float2 o = make_float2(v0 + s_c1[cl], v1 + s_c1[cl + 1]);
                    *reinterpret_cast<float2*>(
                        CoutF + (size_t)(rowA0 + rl) * C_DIM + colB0 + cl) = o;
                }
            }
        }
    }
}

// ---------------- stage1 body (one batch b, one 256-channel part) -------------
__device__ __forceinline__ void stage1_body(
        const float* __restrict__ x, float* s_fc1, float* s_w, float* s_b,
        const float* __restrict__ ln1w, const float* __restrict__ ln1b,
        const float* __restrict__ fc1w, int b, int cpart) {
    int tid = threadIdx.x;
    if (tid < 64) s_fc1[tid] = fc1w[tid];
    if (tid < 8) { s_w[tid] = ln1w[tid]; s_b[tid] = ln1b[tid]; }
    __syncthreads();

    int c = cpart * 256 + tid;
    const float* xb = x + (size_t)b * NTOK * C_DIM;
    __half* rowbase = g_xfuse + (size_t)b * NTOK * K2DIM;

    float M[64];
    #pragma unroll
    for (int n = 0; n < 64; n++) M[n] = __ldcs(xb + n * C_DIM + c);

    #pragma unroll
    for (int n = 0; n < 64; n++)
        st_half_cs(&rowbase[(size_t)n * K2DIM + c], __float2half_rn(M[n]));

    #pragma unroll
    for (int j = 0; j < 8; j++) {
        float m = 0.f;
        #pragma unroll
        for (int t = 0; t < 8; t++) m += M[t * 8 + j];
        m *= 0.125f;
        float v = 0.f;
        #pragma unroll
        for (int t = 0; t < 8; t++) { float d = M[t * 8 + j] - m; v += d * d; }
        float rs = rsqrtf(v * 0.125f + 1e-5f);
        float ln[8];
        #pragma unroll
        for (int t = 0; t < 8; t++)
            ln[t] = (M[t * 8 + j] - m) * rs * s_w[t] + s_b[t];
        float acol[8];
        #pragma unroll
        for (int io = 0; io < 8; io++) {
            float a = 0.f;
            #pragma unroll
            for (int t = 0; t < 8; t++) a += s_fc1[io * 8 + t] * ln[t];
            acol[io] = gelu_t(a);
        }
        #pragma unroll
        for (int i = 0; i < 8; i++) {
            float xh = 0.f;
            #pragma unroll
            for (int t = 0; t < 8; t++) xh += M[i * 8 + t] * acol[t];
            st_half_cs(&rowbase[(size_t)(i * 8 + j) * K2DIM + C_DIM + c],
                       __float2half_rn(xh));
        }
    }
    #pragma unroll
    for (int i = 0; i < 8; i++) {
        float m = 0.f;
        #pragma unroll
        for (int t = 0; t < 8; t++) m += M[i * 8 + t];
        m *= 0.125f;
        float v = 0.f;
        #pragma unroll
        for (int t = 0; t < 8; t++) { float d = M[i * 8 + t] - m; v += d * d; }
        float rs = rsqrtf(v * 0.125f + 1e-5f);
        float ln[8];
        #pragma unroll
        for (int t = 0; t < 8; t++)
            ln[t] = (M[i * 8 + t] - m) * rs * s_w[t] + s_b[t];
        float wrow[8];
        #pragma unroll
        for (int jo = 0; jo < 8; jo++) {
            float a = 0.f;
            #pragma unroll
            for (int t = 0; t < 8; t++) a += ln[t] * s_fc1[jo * 8 + t];
            wrow[jo] = gelu_t(a);
        }
        #pragma unroll
        for (int j = 0; j < 8; j++) {
            float xw = 0.f;
            #pragma unroll
            for (int t = 0; t < 8; t++) xw += wrow[t] * M[t * 8 + j];
            st_half_cs(&rowbase[(size_t)(i * 8 + j) * K2DIM + 2 * C_DIM + c],
                       __float2half_rn(xw));
        }
    }
}

// ---------------- prep body (one output row o) --------------------------------
__device__ __forceinline__ void prep_body(
        const float* __restrict__ fc2, const float* __restrict__ w2,
        const float* __restrict__ b2, const float* __restrict__ proj,
        float* s_red, int o) {
    int tid = threadIdx.x;
    float cs = 0.f, bs = 0.f;
    for (int k = tid; k < K2DIM; k += 256) {
        float f = __ldcs(fc2 + o * K2DIM + k);
        float wk = w2[k];
        st_half_cs(&g_fc2p[o * K2DIM + k], __float2half_rn(f * wk));
        cs += f * wk;
        bs += f * b2[k];
    }
    for (int k = tid; k < C_DIM; k += 256)
        st_half_cs(&g_projp[o * C_DIM + k],
                   __float2half_rn(__ldcs(proj + o * C_DIM + k)));

    #pragma unroll
    for (int off = 16; off; off >>= 1) {
        cs += __shfl_down_sync(0xffffffffu, cs, off);
        bs += __shfl_down_sync(0xffffffffu, bs, off);
    }
    int wid = tid >> 5, lane = tid & 31;
    if (lane == 0) { s_red[wid] = cs; s_red[8 + wid] = bs; }
    __syncthreads();
    if (tid == 0) {
        float c2 = 0.f, bb = 0.f;
        for (int i = 0; i < 8; i++) { c2 += s_red[i]; bb += s_red[8 + i]; }
        g_colsum[o] = c2; g_bsum[o] = bb;
    }
}

// ---------------- single persistent kernel ------------------------------------
__global__ __launch_bounds__(GTHREADS, 2) void megakernel(
        const float* __restrict__ x,
        const float* __restrict__ ln1w, const float* __restrict__ ln1b,
        const float* __restrict__ fc1w,
        const float* __restrict__ fc2, const float* __restrict__ w2,
        const float* __restrict__ b2, const float* __restrict__ proj,
        const float* __restrict__ projb, float* __restrict__ out) {
    extern __shared__ __half smh[];
    __shared__ float s_m[BM], s_r[BM], s_c0[BN], s_c1[BN];
    __shared__ float s_fc1[64], s_w[8], s_b[8], s_red[16];
    __shared__ unsigned s_tile;

    uint32_t smem_u = (uint32_t)__cvta_generic_to_shared(smh);
    int tid = threadIdx.x;

    for (;;) {
        if (tid == 0) s_tile = atomicAdd(&g_queue, 1u);
        __syncthreads();
        unsigned t = s_tile;
        __syncthreads();
        if (t >= N_TILES) return;

        if (t < T_PREP) {
            prep_body(fc2, w2, b2, proj, s_red, (int)t);
            __threadfence();
            __syncthreads();
            if (tid == 0) atomicAdd(&g_pdone[t >> 7], 1u);
        } else if (t < OFF_K2) {
            unsigned j = t - OFF_S1;
            int b = (int)(j / 3), cpart = (int)(j % 3);
            stage1_body(x, s_fc1, s_w, s_b, ln1w, ln1b, fc1w, b, cpart);
            __threadfence();
            __syncthreads();
            if (tid == 0) atomicAdd(&g_s1done[b >> 1], 1u);
        } else if (t < OFF_K3) {
            unsigned j = t - OFF_K2;
            int bx = (int)(j % 6), by = (int)(j / 6);
            if (tid == 0) {
                while (*(volatile unsigned*)&g_s1done[by] < 6u ||
                       *(volatile unsigned*)&g_pdone[bx] < 128u) __nanosleep(64);
            }
            __syncthreads();
            __threadfence();
            gemm_tile<K2DIM, true>(smem_u, s_m, s_r, s_c0, s_c1,
                                   g_xfuse, g_fc2p, nullptr, nullptr, g_y, bx, by);
            __threadfence();
            __syncthreads();
            if (tid == 0) atomicAdd(&g_mdone[by], 1u);
        } else {
            unsigned j = t - OFF_K3;
            int bx = (int)(j % 6), by = (int)(j / 6);
            if (tid == 0) {
                while (*(volatile unsigned*)&g_mdone[by] < 6u ||
                       *(volatile unsigned*)&g_pdone[bx] < 128u) __nanosleep(64);
            }
            __syncthreads();
            __threadfence();
            gemm_tile<C_DIM, false>(smem_u, s_m, s_r, s_c0, s_c1,
                                    g_y, g_projp, projb, out, nullptr, bx, by);
            __syncthreads();
        }
    }
}

// ---------------- launch ----------------
extern "C" void kernel_launch(void* const* d_in, const int* in_sizes, int n_in,
                              void* d_out, int out_size) {
    const float* x     = (const float*)d_in[0];
    const float* ln1w  = (const float*)d_in[1];
    const float* ln1b  = (const float*)d_in[2];
    const float* fc1w  = (const float*)d_in[3];
    const float* ln2w  = (const float*)d_in[4];
    const float* ln2b  = (const float*)d_in[5];
    const float* fc2w  = (const float*)d_in[6];
    const float* projw = (const float*)d_in[7];
    const float* projb = (const float*)d_in[8];
    float* out = (float*)d_out;

    cudaFuncSetAttribute(megakernel,
                         cudaFuncAttributeMaxDynamicSharedMemorySize, SMEM_BYTES);

    // reset persistent-queue state (async memset, graph-capturable)
    void* a0; cudaGetSymbolAddress(&a0, g_queue);
    void* a1; cudaGetSymbolAddress(&a1, g_pdone);
    void* a2; cudaGetSymbolAddress(&a2, g_s1done);
    void* a3; cudaGetSymbolAddress(&a3, g_mdone);
    cudaMemsetAsync(a0, 0, sizeof(unsigned));
    cudaMemsetAsync(a1, 0, sizeof(unsigned) * 6);
    cudaMemsetAsync(a2, 0, sizeof(unsigned) * (TOKENS / 128));
    cudaMemsetAsync(a3, 0, sizeof(unsigned) * (TOKENS / 128));

    megakernel<<<296, GTHREADS, SMEM_BYTES>>>(x, ln1w, ln1b, fc1w,
                                              fc2w, ln2w, ln2b, projw,
                                              projb, out);
}

// round 16
// speedup vs baseline: 1.0337x; 1.0337x over previous
#include <cuda_runtime.h>
#include <cuda_fp16.h>
#include <cstdint>
#include <math.h>

// Problem constants
#define BATCH   512
#define NTOK    64
#define C_DIM   768
#define K2DIM   2304          // 3*C
#define TOKENS  (BATCH * NTOK)   // 32768

// ---------------- device scratch (no allocation allowed) ----------------
__device__ __half g_xfuse[(size_t)TOKENS * K2DIM];   // [token][3C], fp16
__device__ __half g_y[(size_t)TOKENS * C_DIM];       // stage-2 output, fp16
__device__ __half g_fc2p[C_DIM * K2DIM];             // fc2 * ln2_w, fp16
__device__ __half g_projp[C_DIM * C_DIM];            // proj_w, fp16
__device__ float  g_colsum[C_DIM];                   // sum_k ln2_w[k]*fc2[o,k]
__device__ float  g_bsum[C_DIM];                     // sum_k ln2_b[k]*fc2[o,k]
__device__ unsigned g_queue;                         // persistent work ticket
__device__ unsigned g_mdone[TOKENS / 128];           // per-M-block K2 tiles done (target 6)

#define N_K2_TILES 1536        // 6 x 256
#define N_K3_TILES 1536
#define N_TILES    (N_K2_TILES + N_K3_TILES)

// ---------------- helpers ----------------
__device__ __forceinline__ float tanh_fast(float x) {
    float y;
    asm("tanh.approx.f32 %0, %1;" : "=f"(y) : "f"(x));
    return y;
}
__device__ __forceinline__ float gelu_t(float x) {
    float u = 0.7978845608028654f * (x + 0.044715f * x * x * x);
    return 0.5f * x * (1.0f + tanh_fast(u));
}
__device__ __forceinline__ void st_half_cs(__half* p, __half v) {
    short b = *reinterpret_cast<short*>(&v);
    __stcs(reinterpret_cast<short*>(p), b);
}

// ---------------- K1: fused stage1 (blocks 0..1535) + weight prep (1536..2303) -
__global__ __launch_bounds__(256, 2) void stage1_prep(
        const float* __restrict__ x,
        const float* __restrict__ ln1w, const float* __restrict__ ln1b,
        const float* __restrict__ fc1w,
        const float* __restrict__ fc2, const float* __restrict__ w2,
        const float* __restrict__ b2, const float* __restrict__ proj) {
    int bid = blockIdx.x;
    int tid = threadIdx.x;

    if (bid >= 1536) {
        int o = bid - 1536;
        float cs = 0.f, bs = 0.f;
        for (int k = tid; k < K2DIM; k += 256) {
            float f = __ldcs(fc2 + o * K2DIM + k);
            float wk = w2[k];
            st_half_cs(&g_fc2p[o * K2DIM + k], __float2half_rn(f * wk));
            cs += f * wk;
            bs += f * b2[k];
        }
        for (int k = tid; k < C_DIM; k += 256)
            st_half_cs(&g_projp[o * C_DIM + k],
                       __float2half_rn(__ldcs(proj + o * C_DIM + k)));

        __shared__ float scs[8], sbs[8];
        #pragma unroll
        for (int off = 16; off; off >>= 1) {
            cs += __shfl_down_sync(0xffffffffu, cs, off);
            bs += __shfl_down_sync(0xffffffffu, bs, off);
        }
        int wid = tid >> 5, lane = tid & 31;
        if (lane == 0) { scs[wid] = cs; sbs[wid] = bs; }
        __syncthreads();
        if (tid == 0) {
            float c2 = 0.f, bb = 0.f;
            for (int i = 0; i < 8; i++) { c2 += scs[i]; bb += sbs[i]; }
            g_colsum[o] = c2; g_bsum[o] = bb;
        }
        return;
    }

    __shared__ float s_fc1[64], s_w[8], s_b[8];
    if (tid < 64) s_fc1[tid] = fc1w[tid];
    if (tid < 8) { s_w[tid] = ln1w[tid]; s_b[tid] = ln1b[tid]; }
    __syncthreads();

    int b = bid & 511;
    int c = (bid >> 9) * 256 + tid;
    const float* xb = x + (size_t)b * NTOK * C_DIM;
    __half* rowbase = g_xfuse + (size_t)b * NTOK * K2DIM;

    float M[64];
    #pragma unroll
    for (int n = 0; n < 64; n++) M[n] = __ldcs(xb + n * C_DIM + c);

    #pragma unroll
    for (int n = 0; n < 64; n++)
        st_half_cs(&rowbase[(size_t)n * K2DIM + c], __float2half_rn(M[n]));

    #pragma unroll
    for (int j = 0; j < 8; j++) {
        float m = 0.f;
        #pragma unroll
        for (int t = 0; t < 8; t++) m += M[t * 8 + j];
        m *= 0.125f;
        float v = 0.f;
        #pragma unroll
        for (int t = 0; t < 8; t++) { float d = M[t * 8 + j] - m; v += d * d; }
        float rs = rsqrtf(v * 0.125f + 1e-5f);
        float ln[8];
        #pragma unroll
        for (int t = 0; t < 8; t++)
            ln[t] = (M[t * 8 + j] - m) * rs * s_w[t] + s_b[t];
        float acol[8];
        #pragma unroll
        for (int io = 0; io < 8; io++) {
            float a = 0.f;
            #pragma unroll
            for (int t = 0; t < 8; t++) a += s_fc1[io * 8 + t] * ln[t];
            acol[io] = gelu_t(a);
        }
        #pragma unroll
        for (int i = 0; i < 8; i++) {
            float xh = 0.f;
            #pragma unroll
            for (int t = 0; t < 8; t++) xh += M[i * 8 + t] * acol[t];
            st_half_cs(&rowbase[(size_t)(i * 8 + j) * K2DIM + C_DIM + c],
                       __float2half_rn(xh));
        }
    }
    #pragma unroll
    for (int i = 0; i < 8; i++) {
        float m = 0.f;
        #pragma unroll
        for (int t = 0; t < 8; t++) m += M[i * 8 + t];
        m *= 0.125f;
        float v = 0.f;
        #pragma unroll
        for (int t = 0; t < 8; t++) { float d = M[i * 8 + t] - m; v += d * d; }
        float rs = rsqrtf(v * 0.125f + 1e-5f);
        float ln[8];
        #pragma unroll
        for (int t = 0; t < 8; t++)
            ln[t] = (M[i * 8 + t] - m) * rs * s_w[t] + s_b[t];
        float wrow[8];
        #pragma unroll
        for (int jo = 0; jo < 8; jo++) {
            float a = 0.f;
            #pragma unroll
            for (int t = 0; t < 8; t++) a += ln[t] * s_fc1[jo * 8 + t];
            wrow[jo] = gelu_t(a);
        }
        #pragma unroll
        for (int j = 0; j < 8; j++) {
            float xw = 0.f;
            #pragma unroll
            for (int t = 0; t < 8; t++) xw += wrow[t] * M[t * 8 + j];
            st_half_cs(&rowbase[(size_t)(i * 8 + j) * K2DIM + 2 * C_DIM + c],
                       __float2half_rn(xw));
        }
    }
}

// ---------------- GEMM tile (R10 745us config) as a device function ----------
#define BM 128
#define BN 128
#define BK 32
#define LDH 40
#define NSLOT 5
#define TILE_H (BM * LDH)
#define STAGE_BYTES (2 * TILE_H * 2)
#define SMEM_BYTES (NSLOT * STAGE_BYTES)      // 102400 B
#define GTHREADS 256

__device__ __forceinline__ void cp16(uint32_t smem, const void* g) {
    asm volatile("cp.async.cg.shared.global [%0], [%1], 16;\n" :: "r"(smem), "l"(g));
}

template<int KDIM, bool FUSE>
__device__ __forceinline__ void gemm_tile(
        uint32_t smem_u, float* s_m, float* s_r, float* s_c0, float* s_c1,
        const __half* __restrict__ Ag, const __half* __restrict__ Bg,
        const float* __restrict__ bias,
        float* __restrict__ CoutF, __half* __restrict__ CoutH,
        int bx, int by) {
    int tid = threadIdx.x;
    int rowA0 = by * BM;
    int colB0 = bx * BN;
    const __half* Abase = Ag + (size_t)rowA0 * KDIM;
    const __half* Bbase = Bg + (size_t)colB0 * KDIM;

    int lr = tid >> 1;
    int lc = (tid & 1) * 16;
    uint32_t sOffA = (uint32_t)((lr * LDH + lc) * 2);
    uint32_t sOffB = sOffA + TILE_H * 2;

    auto load_body = [&](int slot, int kt) {
        uint32_t base = smem_u + (uint32_t)slot * STAGE_BYTES;
        const __half* a0 = Abase + (size_t)lr * KDIM + kt * BK + lc;
        cp16(base + sOffA,      a0);
        cp16(base + sOffA + 16, a0 + 8);
        const __half* b0 = Bbase + (size_t)lr * KDIM + kt * BK + lc;
        cp16(base + sOffB,      b0);
        cp16(base + sOffB + 16, b0 + 8);
    };

    const int KT = KDIM / BK;
    #pragma unroll
    for (int p = 0; p < 3; p++) {
        load_body(p, p);
        asm volatile("cp.async.commit_group;\n");
    }

    int wid = tid >> 5, lane = tid & 31;
    int wm = (wid & 1) * 64;
    int wn = (wid >> 1) * 32;

    uint32_t offA[4];
    #pragma unroll
    for (int mm = 0; mm < 4; mm++) {
        int row = wm + mm * 16 + (lane & 15);
        int kb  = lane >> 4;
        offA[mm] = (uint32_t)((row * LDH + kb * 8) * 2);
    }
    uint32_t offB[2];
    #pragma unroll
    for (int nn2 = 0; nn2 < 2; nn2++) {
        int n  = wn + nn2 * 16 + (lane & 7) + ((lane >> 4) ? 8 : 0);
        int kb = (lane >> 3) & 1;
        offB[nn2] = (uint32_t)((n * LDH + kb * 8) * 2 + TILE_H * 2);
    }

    float acc[4][4][4];
    #pragma unroll
    for (int a = 0; a < 4; a++)
        #pragma unroll
        for (int b2 = 0; b2 < 4; b2++)
            #pragma unroll
            for (int c2 = 0; c2 < 4; c2++) acc[a][b2][c2] = 0.f;

    float rsum = 0.f, rsq = 0.f;
    int srow = tid & 127, skh = (tid >> 7) * 16;
    uint32_t statOff = (uint32_t)((srow * LDH + skh) * 2);

    auto compute_stage = [&](int slot) {
        uint32_t stage = smem_u + (uint32_t)slot * STAGE_BYTES;

        if (FUSE) {
            uint4 q0, q1;
            asm volatile("ld.shared.v4.u32 {%0,%1,%2,%3}, [%4];"
                         : "=r"(q0.x), "=r"(q0.y), "=r"(q0.z), "=r"(q0.w)
                         : "r"(stage + statOff));
            asm volatile("ld.shared.v4.u32 {%0,%1,%2,%3}, [%4];"
                         : "=r"(q1.x), "=r"(q1.y), "=r"(q1.z), "=r"(q1.w)
                         : "r"(stage + statOff + 16));
            const uint32_t wv[8] = {q0.x, q0.y, q0.z, q0.w, q1.x, q1.y, q1.z, q1.w};
            #pragma unroll
            for (int wq = 0; wq < 8; wq++) {
                __half2 hv = *reinterpret_cast<const __half2*>(&wv[wq]);
                float2 f = __half22float2(hv);
                rsum += f.x + f.y;
                rsq  += f.x * f.x + f.y * f.y;
            }
        }

        #pragma unroll
        for (int kk = 0; kk < BK; kk += 16) {
            uint32_t af[4][4], bf[2][4];
            #pragma unroll
            for (int mm = 0; mm < 4; mm++)
                asm volatile(
                    "ldmatrix.sync.aligned.m8n8.x4.shared.b16 {%0,%1,%2,%3}, [%4];\n"
                    : "=r"(af[mm][0]), "=r"(af[mm][1]), "=r"(af[mm][2]), "=r"(af[mm][3])
                    : "r"(stage + offA[mm] + kk * 2));
            #pragma unroll
            for (int nn2 = 0; nn2 < 2; nn2++)
                asm volatile(
                    "ldmatrix.sync.aligned.m8n8.x4.shared.b16 {%0,%1,%2,%3}, [%4];\n"
                    : "=r"(bf[nn2][0]), "=r"(bf[nn2][1]), "=r"(bf[nn2][2]), "=r"(bf[nn2][3])
                    : "r"(stage + offB[nn2] + kk * 2));

            #pragma unroll
            for (int mm = 0; mm < 4; mm++)
                #pragma unroll
                for (int nn = 0; nn < 4; nn++) {
                    const uint32_t b0 = bf[nn >> 1][(nn & 1) * 2 + 0];
                    const uint32_t b1 = bf[nn >> 1][(nn & 1) * 2 + 1];
                    asm volatile(
                        "mma.sync.aligned.m16n8k16.row.col.f32.f16.f16.f32 "
                        "{%0,%1,%2,%3}, {%4,%5,%6,%7}, {%8,%9}, {%0,%1,%2,%3};\n"
                        : "+f"(acc[mm][nn][0]), "+f"(acc[mm][nn][1]),
                          "+f"(acc[mm][nn][2]), "+f"(acc[mm][nn][3])
                        : "r"(af[mm][0]), "r"(af[mm][1]), "r"(af[mm][2]), "r"(af[mm][3]),
                          "r"(b0), "r"(b1));
                }
        }
    };

    int slotC = 0, slotP = 3;
    for (int s = 0; s < KT; s += 2) {
        asm volatile("cp.async.wait_group %0;\n" :: "n"(1));
        __syncthreads();

        if (s + 3 < KT) load_body(slotP, s + 3);
        asm volatile("cp.async.commit_group;\n");
        int slotP2 = slotP + 1; if (slotP2 >= NSLOT) slotP2 -= NSLOT;
        if (s + 4 < KT) load_body(slotP2, s + 4);
        asm volatile("cp.async.commit_group;\n");

        compute_stage(slotC);
        int slotC2 = slotC + 1; if (slotC2 >= NSLOT) slotC2 -= NSLOT;
        compute_stage(slotC2);

        slotC += 2; if (slotC >= NSLOT) slotC -= NSLOT;
        slotP += 2; if (slotP >= NSLOT) slotP -= NSLOT;
    }
    // drain remaining cp.async groups so the next tile can reuse smem safely
    asm volatile("cp.async.wait_group 0;\n");

    // ---- epilogue ----
    __syncthreads();
    if (FUSE) {
        if (tid < 128) { s_m[tid] = rsum; s_r[tid] = rsq; }
        __syncthreads();
        if (tid >= 128) { s_m[tid - 128] += rsum; s_r[tid - 128] += rsq; }
        __syncthreads();
        if (tid < 128) {
            float mu  = s_m[tid] * (1.0f / (float)KDIM);
            float var = s_r[tid] * (1.0f / (float)KDIM) - mu * mu;
            s_m[tid] = mu;
            s_r[tid] = rsqrtf(var + 1e-5f);
            s_c0[tid] = g_colsum[colB0 + tid];
            s_c1[tid] = g_bsum[colB0 + tid];
        }
        __syncthreads();
    } else {
        if (tid < 128) s_c1[tid] = bias[colB0 + tid];
        __syncthreads();
    }

    int g = lane >> 2, t4 = lane & 3;
    #pragma unroll
    for (int mm = 0; mm < 4; mm++) {
        #pragma unroll
        for (int nn = 0; nn < 4; nn++) {
            #pragma unroll
            for (int rh = 0; rh < 2; rh++) {
                int rl = wm + mm * 16 + g + rh * 8;
                int cl = wn + nn * 8 + 2 * t4;
                float v0 = acc[mm][nn][rh * 2 + 0];
                float v1 = acc[mm][nn][rh * 2 + 1];
                if (FUSE) {
                    float p0 = s_r[rl] * (v0 - s_m[rl] * s_c0[cl])     + s_c1[cl];
                    float p1 = s_r[rl] * (v1 - s_m[rl] * s_c0[cl + 1]) + s_c1[cl + 1];
                    __half2 o = __floats2half2_rn(gelu_t(p0), gelu_t(p1));
                    *reinterpret_cast<__half2*>(
                        CoutH + (size_t)(rowA0 + rl) * C_DIM + colB0 + cl) = o;
                } else {
                    float2 o = make_float2(v0 + s_c1[cl], v1 + s_c1[cl + 1]);
                    *reinterpret_cast<float2*>(
                        CoutF + (size_t)(rowA0 + rl) * C_DIM + colB0 + cl) = o;
                }
            }
        }
    }
}

// ---------------- persistent fused K2+K3 -------------------------------------
// Work queue: tickets 0..1535 = K2 tiles (n fast), 1536..3071 = K3 tiles.
// K3 tile m waits for its 6 producer K2 tiles via g_mdone[m].
__global__ __launch_bounds__(GTHREADS, 2) void gemm_fused(
        const float* __restrict__ projb, float* __restrict__ out) {
    extern __shared__ __half smh[];
    __shared__ float s_m[BM], s_r[BM], s_c0[BN], s_c1[BN];
    __shared__ unsigned s_tile;

    uint32_t smem_u = (uint32_t)__cvta_generic_to_shared(smh);
    int tid = threadIdx.x;

    for (;;) {
        if (tid == 0) s_tile = atomicAdd(&g_queue, 1u);
        __syncthreads();
        unsigned t = s_tile;
        __syncthreads();          // protect s_tile before next iteration's write
        if (t >= N_TILES) return;

        if (t < N_K2_TILES) {
            int bx = t % 6, by = t / 6;
            gemm_tile<K2DIM, true>(smem_u, s_m, s_r, s_c0, s_c1,
                                   g_xfuse, g_fc2p, nullptr, nullptr, g_y, bx, by);
            __threadfence();      // publish g_y writes
            __syncthreads();
            if (tid == 0) atomicAdd(&g_mdone[by], 1u);
        } else {
            unsigned j = t - N_K2_TILES;
            int bx = j % 6, by = j / 6;
            if (tid == 0) {
                while (*(volatile unsigned*)&g_mdone[by] < 6u) __nanosleep(64);
            }
            __syncthreads();
            __threadfence();      // acquire: order poll before g_y reads
            gemm_tile<C_DIM, false>(smem_u, s_m, s_r, s_c0, s_c1,
                                    g_y, g_projp, projb, out, nullptr, bx, by);
            __syncthreads();
        }
    }
}

// ---------------- launch ----------------
extern "C" void kernel_launch(void* const* d_in, const int* in_sizes, int n_in,
                              void* d_out, int out_size) {
    const float* x     = (const float*)d_in[0];
    const float* ln1w  = (const float*)d_in[1];
    const float* ln1b  = (const float*)d_in[2];
    const float* fc1w  = (const float*)d_in[3];
    const float* ln2w  = (const float*)d_in[4];
    const float* ln2b  = (const float*)d_in[5];
    const float* fc2w  = (const float*)d_in[6];
    const float* projw = (const float*)d_in[7];
    const float* projb = (const float*)d_in[8];
    float* out = (float*)d_out;

    cudaFuncSetAttribute(gemm_fused,
                         cudaFuncAttributeMaxDynamicSharedMemorySize, SMEM_BYTES);

    // reset persistent-queue state (async memset is capturable, no allocation)
    void* qaddr;  cudaGetSymbolAddress(&qaddr, g_queue);
    void* maddr;  cudaGetSymbolAddress(&maddr, g_mdone);
    cudaMemsetAsync(qaddr, 0, sizeof(unsigned));
    cudaMemsetAsync(maddr, 0, sizeof(unsigned) * (TOKENS / 128));

    stage1_prep<<<1536 + C_DIM, 256>>>(x, ln1w, ln1b, fc1w,
                                       fc2w, ln2w, ln2b, projw);

    gemm_fused<<<296, GTHREADS, SMEM_BYTES>>>(projb, out);
}